// round 16
// baseline (speedup 1.0000x reference)
#include <cuda_runtime.h>

#define BATCH 128
#define TSTEPS 1024
#define IDIM 256
#define HDIM 512
#define GDIM 2048
#define REC_CHUNK 128
#define HB (HDIM * BATCH)
typedef unsigned long long ull;

__device__ float g_xw[(size_t)TSTEPS * GDIM * BATCH];  // [t][g'][b]
__device__ float g_W2[128 * 512 * 4 * 8];              // [cta][j][kl][gate*(w,w)]
__device__ float g_Wih_t[IDIM * GDIM];                 // [i][g']
__device__ float g_bias[GDIM];
__device__ float g_hP[2 * HB];                         // [buf][j][b]
__device__ float g_c[BATCH * HDIM];
__device__ unsigned g_bar;

__device__ __forceinline__ ull pk2(float lo, float hi) {
    ull r; asm("mov.b64 %0, {%1, %2};" : "=l"(r) : "f"(lo), "f"(hi)); return r;
}
__device__ __forceinline__ void fma2(ull& d, ull a, ull b) {
    asm("fma.rn.f32x2 %0, %1, %2, %0;" : "+l"(d) : "l"(a), "l"(b));
}
__device__ __forceinline__ ull add2(ull a, ull b) {
    ull r; asm("add.rn.f32x2 %0, %1, %2;" : "=l"(r) : "l"(a), "l"(b)); return r;
}
__device__ __forceinline__ void ldg_nc2(ull& a, ull& b, const float* p) {
    asm("ld.global.nc.v2.u64 {%0,%1}, [%2];" : "=l"(a), "=l"(b) : "l"(p));
}

// ------------------------------ init --------------------------------------
__global__ void init_kernel(const float* __restrict__ W_ih,
                            const float* __restrict__ W_hh,
                            const float* __restrict__ b_ih,
                            const float* __restrict__ b_hh) {
    int idx = blockIdx.x * blockDim.x + threadIdx.x;
    int stride = gridDim.x * blockDim.x;
    for (int p = idx; p < 128 * 512 * 16; p += stride) {
        int cta = p >> 13, r = p & 8191;
        int j = r >> 4, kl = (r >> 2) & 3, gate = r & 3;
        float v = W_hh[(size_t)(gate * 512 + cta * 4 + kl) * 512 + j];
        g_W2[(size_t)p * 2] = v;
        g_W2[(size_t)p * 2 + 1] = v;
    }
    for (int p = idx; p < IDIM * GDIM; p += stride) {
        int i = p >> 11, g = p & 2047;
        int gate = g & 3, kl = (g >> 2) & 3, khid = ((g >> 4) << 2) + kl;
        g_Wih_t[p] = W_ih[(size_t)(gate * 512 + khid) * 256 + i];
    }
    for (int p = idx; p < GDIM; p += stride) {
        int gate = p & 3, kl = (p >> 2) & 3, khid = ((p >> 4) << 2) + kl;
        g_bias[p] = b_ih[gate * 512 + khid] + b_hh[gate * 512 + khid];
    }
    if (idx == 0) g_bar = 0u;
}

// ----------------------------- xW GEMM (f32x2) -----------------------------
#define GM_BK 32
#define AS_STRIDE 68
__global__ __launch_bounds__(256) void xw_gemm(const float* __restrict__ x) {
    __shared__ float As[GM_BK * AS_STRIDE];
    __shared__ float Bs[GM_BK * 128];
    const int by = blockIdx.y;
    const int t = by >> 1, b0 = (by & 1) * 64;
    const int n0 = blockIdx.x * 128;
    const int tid = threadIdx.x;
    const int tm = tid & 15, tn8 = (tid >> 4) * 8;
    const float* xbase = x + ((size_t)b0 * TSTEPS + t) * IDIM;

    ull acc[2][8];
    #pragma unroll
    for (int mp = 0; mp < 2; mp++)
        #pragma unroll
        for (int n = 0; n < 8; n++) acc[mp][n] = 0ull;

    for (int k0 = 0; k0 < IDIM; k0 += GM_BK) {
        #pragma unroll
        for (int l = 0; l < 2; l++) {
            int idx4 = tid + l * 256;
            int k4 = (idx4 & 7) * 4, row = idx4 >> 3;
            float4 v = *(const float4*)(xbase + (size_t)row * (TSTEPS * IDIM) + k0 + k4);
            As[(k4 + 0) * AS_STRIDE + row] = v.x;
            As[(k4 + 1) * AS_STRIDE + row] = v.y;
            As[(k4 + 2) * AS_STRIDE + row] = v.z;
            As[(k4 + 3) * AS_STRIDE + row] = v.w;
        }
        #pragma unroll
        for (int l = 0; l < 4; l++) {
            int idx4 = tid + l * 256;
            int n4 = (idx4 & 31) * 4, k = idx4 >> 5;
            *(float4*)(&Bs[k * 128 + n4]) =
                *(const float4*)(g_Wih_t + (size_t)(k0 + k) * GDIM + n0 + n4);
        }
        __syncthreads();
        #pragma unroll
        for (int k = 0; k < GM_BK; k++) {
            ulonglong2 ap = *(const ulonglong2*)(&As[k * AS_STRIDE + tm * 4]);
            float4 p = *(const float4*)(&Bs[k * 128 + tn8]);
            float4 q = *(const float4*)(&Bs[k * 128 + tn8 + 4]);
            float bv[8] = {p.x, p.y, p.z, p.w, q.x, q.y, q.z, q.w};
            #pragma unroll
            for (int n = 0; n < 8; n++) {
                ull s = pk2(bv[n], bv[n]);
                fma2(acc[0][n], ap.x, s);
                fma2(acc[1][n], ap.y, s);
            }
        }
        __syncthreads();
    }
    #pragma unroll
    for (int n = 0; n < 8; n++) {
        float bz = g_bias[n0 + tn8 + n];
        ull bz2 = pk2(bz, bz);
        ulonglong2 o;
        o.x = add2(acc[0][n], bz2);
        o.y = add2(acc[1][n], bz2);
        *(ulonglong2*)(g_xw + ((size_t)t * GDIM + n0 + tn8 + n) * BATCH + b0 + tm * 4) = o;
    }
}

// --------------------------- recurrent ------------------------------------
// Compute role: warp = je (32-j slab), lane = bq (b-quad; 32 lanes = all 128 b,
//   h read once per CTA). Thread: 4 kl x 4 gates x 4 b = 32 f32x2 accs.
//   Per j: 1 LDG.128 h (.cg) + 8 uniform LDG.128 W (.nc, L1-resident) + 32 FFMA2.
// Reduce role: thread (klR = tid>>7, bR = tid&127): sum 16 je partials/gate,
//   activations, c in register, st.cg h.
__global__ __launch_bounds__(512, 1) void lstm_rec(int t0) {
    extern __shared__ float P[];   // 32768 floats (128 KB): [je][kl*4+g][b]

    const int cta = blockIdx.x, tid = threadIdx.x;

    const int je = tid >> 5;
    const int bq = tid & 31;
    const int jbase = je * 32;
    const float* wslab = g_W2 + (size_t)cta * 16384 + (size_t)jbase * 32;
    float* Pw = P + je * 2048 + bq * 4;      // + (kl*4+g)*128

    const int klR = tid >> 7, bR = tid & 127;
    const int cell = bR * HDIM + cta * 4 + klR;
    const float* Pr = P + klR * 512 + bR;    // + e*2048 + g*128
    const float* xwb = g_xw + (size_t)(cta * 16 + klR * 4) * BATCH + bR;
    float* hOut = g_hP + (size_t)(cta * 4 + klR) * BATCH + bR;

    float creg = (t0 == 0) ? 0.0f : g_c[cell];

    float xv0, xv1, xv2, xv3;
    {
        const float* xp = xwb + (size_t)t0 * (GDIM * BATCH);
        xv0 = __ldcg(xp); xv1 = __ldcg(xp + BATCH);
        xv2 = __ldcg(xp + 2 * BATCH); xv3 = __ldcg(xp + 3 * BATCH);
    }

    for (int tl = 0; tl < REC_CHUNK; tl++) {
        const int t = t0 + tl;
        ull A[16][2];   // [kl*4+g][b-pair]
        #pragma unroll
        for (int q = 0; q < 16; q++) { A[q][0] = 0ull; A[q][1] = 0ull; }

        if (t > 0) {
            const float* hb = g_hP + (size_t)(t & 1) * HB + (size_t)jbase * BATCH + bq * 4;
            ulonglong2 u[4];
            #pragma unroll
            for (int p = 0; p < 4; p++)
                u[p] = __ldcg((const ulonglong2*)(hb + (size_t)p * BATCH));
            const float* wj = wslab;
            #pragma unroll 4
            for (int jj = 0; jj < 32; jj++) {
                ulonglong2 cu = u[jj & 3];
                if (jj + 4 < 32)
                    u[jj & 3] = __ldcg((const ulonglong2*)(hb + (size_t)(jj + 4) * BATCH));
                #pragma unroll
                for (int kl = 0; kl < 4; kl++) {
                    ull w0, w1, w2, w3;
                    ldg_nc2(w0, w1, wj + kl * 8);
                    ldg_nc2(w2, w3, wj + kl * 8 + 4);
                    fma2(A[kl*4+0][0], cu.x, w0); fma2(A[kl*4+0][1], cu.y, w0);
                    fma2(A[kl*4+1][0], cu.x, w1); fma2(A[kl*4+1][1], cu.y, w1);
                    fma2(A[kl*4+2][0], cu.x, w2); fma2(A[kl*4+2][1], cu.y, w2);
                    fma2(A[kl*4+3][0], cu.x, w3); fma2(A[kl*4+3][1], cu.y, w3);
                }
                wj += 32;
            }
        }

        #pragma unroll
        for (int q = 0; q < 16; q++) {
            ulonglong2 v; v.x = A[q][0]; v.y = A[q][1];
            *(ulonglong2*)(Pw + q * 128) = v;
        }
        __syncthreads();

        float s0 = xv0, s1 = xv1, s2 = xv2, s3 = xv3;
        #pragma unroll
        for (int e = 0; e < 16; e++) {
            const float* pp = Pr + e * 2048;
            s0 += pp[0]; s1 += pp[128]; s2 += pp[256]; s3 += pp[384];
        }

        float ig = __fdividef(1.0f, 1.0f + __expf(-s0));
        float fg = __fdividef(1.0f, 1.0f + __expf(-s1));
        float gg = 1.0f - __fdividef(2.0f, __expf(2.0f * s2) + 1.0f);
        float og = __fdividef(1.0f, 1.0f + __expf(-s3));
        creg = fg * creg + ig * gg;
        float th = 1.0f - __fdividef(2.0f, __expf(2.0f * creg) + 1.0f);
        float hv = og * th;

        float* hp = hOut + (size_t)((t + 1) & 1) * HB;
        asm volatile("st.global.cg.f32 [%0], %1;" :: "l"(hp), "f"(hv) : "memory");

        if (tl + 1 < REC_CHUNK) {
            const float* xp = xwb + (size_t)(t + 1) * (GDIM * BATCH);
            xv0 = __ldcg(xp); xv1 = __ldcg(xp + BATCH);
            xv2 = __ldcg(xp + 2 * BATCH); xv3 = __ldcg(xp + 3 * BATCH);
        }

        unsigned bar_t = (unsigned)(t + 1) * 128u;
        __syncthreads();
        if (tid == 0) {
            asm volatile("red.release.gpu.global.add.u32 [%0], 1;" :: "l"(&g_bar) : "memory");
            unsigned v;
            do {
                asm volatile("ld.acquire.gpu.global.u32 %0, [%1];" : "=r"(v) : "l"(&g_bar) : "memory");
            } while (v < bar_t);
        }
        __syncthreads();
    }
    g_c[cell] = creg;
}

// ------------------------------- fc ----------------------------------------
__global__ void fc_kernel(const float* __restrict__ fc_w,
                          const float* __restrict__ fc_b,
                          float* __restrict__ out) {
    int b = blockIdx.x, tid = threadIdx.x;     // 128 x 128
    float s = 0.0f;
    for (int j = tid; j < HDIM; j += 128)
        s = fmaf(g_hP[(size_t)j * BATCH + b], fc_w[j], s);
    s += __shfl_down_sync(0xffffffffu, s, 16);
    s += __shfl_down_sync(0xffffffffu, s, 8);
    s += __shfl_down_sync(0xffffffffu, s, 4);
    s += __shfl_down_sync(0xffffffffu, s, 2);
    s += __shfl_down_sync(0xffffffffu, s, 1);
    __shared__ float red[4];
    if ((tid & 31) == 0) red[tid >> 5] = s;
    __syncthreads();
    if (tid == 0) out[b] = red[0] + red[1] + red[2] + red[3] + fc_b[0];
}

// ----------------------------- launcher ------------------------------------
extern "C" void kernel_launch(void* const* d_in, const int* in_sizes, int n_in,
                              void* d_out, int out_size) {
    const float* x    = (const float*)d_in[0];
    const float* W_ih = (const float*)d_in[1];
    const float* W_hh = (const float*)d_in[2];
    const float* b_ih = (const float*)d_in[3];
    const float* b_hh = (const float*)d_in[4];
    const float* fc_w = (const float*)d_in[5];
    const float* fc_b = (const float*)d_in[6];
    float* out = (float*)d_out;

    cudaFuncSetAttribute(lstm_rec, cudaFuncAttributeMaxDynamicSharedMemorySize, 131072);

    init_kernel<<<2048, 256>>>(W_ih, W_hh, b_ih, b_hh);
    dim3 gg(16, 2048);
    xw_gemm<<<gg, 256>>>(x);
    for (int c = 0; c < TSTEPS / REC_CHUNK; c++)
        lstm_rec<<<128, 512, 131072>>>(c * REC_CHUNK);
    fc_kernel<<<128, 128>>>(fc_w, fc_b, out);
}